// round 13
// baseline (speedup 1.0000x reference)
#include <cuda_runtime.h>
#include <cuda_fp16.h>

#define EMBED 128
#define ATTR 25
#define REM 28
#define PAIR_PAD 29                  // coprime with 32 -> conflict-free LDS
#define NLEVEL 50
#define NCOMB 240                    // 2*2*3*20
#define NFULL (NLEVEL * NCOMB)       // 12000 full-product rows

// Base projected tables (fp32, exact)
__device__ float g_Lrow[NLEVEL * EMBED];
__device__ float g_Crow[NCOMB * EMBED];
// Full product table, fp16: 12000 * 128 * 2 B = 3 MB (L2-resident)
__device__ __half g_Full[NFULL * EMBED];

// smem float offsets for staged raw tables
#define S_LVL  0                               // 50*25 = 1250
#define S_TYP  (S_LVL + NLEVEL * ATTR)         // +50
#define S_FEA  (S_TYP + 2 * ATTR)              // +50
#define S_EXC  (S_FEA + 2 * ATTR)              // +75
#define S_PAI  (S_EXC + 3 * ATTR)              // +580 (20*29 padded)
#define S_TOTAL (S_PAI + 20 * PAIR_PAD)        // 2005 floats = 8020 B

// ---- Kernel A: warp per (e, row-block-of-32); lanes span rows.
// Raw tables staged in smem (stride 25/29: conflict-free); W reads broadcast.
__global__ void __launch_bounds__(256)
base_kernel(const float* __restrict__ level_tab,
            const float* __restrict__ type_tab,
            const float* __restrict__ feature_tab,
            const float* __restrict__ exchange_tab,
            const float* __restrict__ pair_tab,
            const float* __restrict__ W,
            const float* __restrict__ b)
{
    __shared__ float sm[S_TOTAL];
    const int tid = threadIdx.x;

    // Stage raw tables (coalesced; ~8 KB total)
    for (int i = tid; i < NLEVEL * ATTR; i += 256) sm[S_LVL + i] = level_tab[i];
    for (int i = tid; i < 2 * ATTR; i += 256)      sm[S_TYP + i] = type_tab[i];
    for (int i = tid; i < 2 * ATTR; i += 256)      sm[S_FEA + i] = feature_tab[i];
    for (int i = tid; i < 3 * ATTR; i += 256)      sm[S_EXC + i] = exchange_tab[i];
    for (int i = tid; i < 20 * REM; i += 256) {
        int p = i / REM, k = i - p * REM;
        sm[S_PAI + p * PAIR_PAD + k] = pair_tab[i];
    }
    __syncthreads();

    const int lane = tid & 31;
    const int task = (blockIdx.x << 3) + (tid >> 5);   // 160 blocks * 8 warps = 1280

    if (task < 256) {
        // level rows: task = e*2 + rb, lanes span r
        int e = task >> 1;
        int r = ((task & 1) << 5) + lane;
        if (r < NLEVEL) {
            const float* wrow = W + e * EMBED;          // broadcast
            const float* lt = sm + S_LVL + r * ATTR;    // stride-25 LDS, conflict-free
            float s0 = 0.f, s1 = 0.f, s2 = 0.f, s3 = 0.f;
            #pragma unroll
            for (int k = 0; k < 24; k += 4) {
                s0 += lt[k]     * wrow[k];
                s1 += lt[k + 1] * wrow[k + 1];
                s2 += lt[k + 2] * wrow[k + 2];
                s3 += lt[k + 3] * wrow[k + 3];
            }
            s0 += lt[24] * wrow[24];
            g_Lrow[r * EMBED + e] = (s0 + s1) + (s2 + s3);
        }
    } else {
        // combined rows: task-256 = e*8 + cb, lanes span c
        int tt = task - 256;
        int e  = tt >> 3;
        int c  = ((tt & 7) << 5) + lane;
        if (c < NCOMB) {
            int p = c % 20, x = (c / 20) % 3, f = (c / 60) % 2, t = c / 120;
            const float* wrow = W + e * EMBED;
            const float* ta = sm + S_TYP + t * ATTR;
            const float* fa = sm + S_FEA + f * ATTR;
            const float* xa = sm + S_EXC + x * ATTR;
            const float* pa = sm + S_PAI + p * PAIR_PAD;
            float s0 = b[e], s1 = 0.f, s2 = 0.f, s3 = 0.f;
            #pragma unroll
            for (int k = 0; k < ATTR; k++) {
                s0 += ta[k] * wrow[25 + k];
                s1 += fa[k] * wrow[50 + k];
                s2 += xa[k] * wrow[75 + k];
            }
            #pragma unroll
            for (int k = 0; k < REM; k++)
                s3 += pa[k] * wrow[100 + k];
            g_Crow[c * EMBED + e] = (s0 + s1) + (s2 + s3);
        }
    }
}

// ---- Kernel B: expand to 12000-row fp16 full-product table (fp32 sum, one fp16 round).
__global__ void __launch_bounds__(256)
expand_kernel()
{
    const int total = NFULL * (EMBED / 2);
    __half2* full2 = reinterpret_cast<__half2*>(g_Full);
    for (int i = blockIdx.x * 256 + threadIdx.x; i < total; i += gridDim.x * 256) {
        int row = i >> 6;          // / 64
        int pos = (i & 63) << 1;
        int l = row / NCOMB;
        int c = row - l * NCOMB;
        float s0 = g_Lrow[l * EMBED + pos]     + g_Crow[c * EMBED + pos];
        float s1 = g_Lrow[l * EMBED + pos + 1] + g_Crow[c * EMBED + pos + 1];
        full2[i] = __floats2half2_rn(s0, s1);
    }
}

// ---- Kernel C: pure streaming gather (unchanged — at DRAM-write floor ~87us).
__global__ void __launch_bounds__(256, 6)
gather_kernel(const int* __restrict__ level_idx,
              const int* __restrict__ type_idx,
              const int* __restrict__ feature_idx,
              const int* __restrict__ exchange_idx,
              const int* __restrict__ pair_idx,
              float4* __restrict__ out, int n)
{
    const uint2* full2 = reinterpret_cast<const uint2*>(g_Full);
    const int lane   = threadIdx.x & 31;
    const int warp   = (blockIdx.x * 256 + threadIdx.x) >> 5;
    const int nwarps = (gridDim.x * 256) >> 5;

    int r = warp * 8;
    const int stride = nwarps * 8;

    for (; r + 7 < n; r += stride) {
        int4 L0 = *reinterpret_cast<const int4*>(level_idx + r);
        int4 L1 = *reinterpret_cast<const int4*>(level_idx + r + 4);
        int4 T0 = *reinterpret_cast<const int4*>(type_idx + r);
        int4 T1 = *reinterpret_cast<const int4*>(type_idx + r + 4);
        int4 F0 = *reinterpret_cast<const int4*>(feature_idx + r);
        int4 F1 = *reinterpret_cast<const int4*>(feature_idx + r + 4);
        int4 X0 = *reinterpret_cast<const int4*>(exchange_idx + r);
        int4 X1 = *reinterpret_cast<const int4*>(exchange_idx + r + 4);
        int4 P0 = *reinterpret_cast<const int4*>(pair_idx + r);
        int4 P1 = *reinterpret_cast<const int4*>(pair_idx + r + 4);

        int l[8] = {L0.x, L0.y, L0.z, L0.w, L1.x, L1.y, L1.z, L1.w};
        int t[8] = {T0.x, T0.y, T0.z, T0.w, T1.x, T1.y, T1.z, T1.w};
        int f[8] = {F0.x, F0.y, F0.z, F0.w, F1.x, F1.y, F1.z, F1.w};
        int x[8] = {X0.x, X0.y, X0.z, X0.w, X1.x, X1.y, X1.z, X1.w};
        int p[8] = {P0.x, P0.y, P0.z, P0.w, P1.x, P1.y, P1.z, P1.w};

        uint2 hv[8];
        #pragma unroll
        for (int k = 0; k < 8; k++) {
            int row = l[k] * NCOMB + ((t[k] * 2 + f[k]) * 3 + x[k]) * 20 + p[k];
            hv[k] = __ldg(&full2[row * 32 + lane]);
        }
        #pragma unroll
        for (int k = 0; k < 8; k++) {
            const __half2* hp = reinterpret_cast<const __half2*>(&hv[k]);
            float2 f0 = __half22float2(hp[0]);
            float2 f1 = __half22float2(hp[1]);
            float4 s;
            s.x = f0.x; s.y = f0.y; s.z = f1.x; s.w = f1.y;
            __stcs(out + (size_t)(r + k) * 32 + lane, s);
        }
    }
    for (; r < n; r++) {   // tail
        int row = level_idx[r] * NCOMB
                + ((type_idx[r] * 2 + feature_idx[r]) * 3 + exchange_idx[r]) * 20
                + pair_idx[r];
        uint2 hv = __ldg(&full2[row * 32 + lane]);
        const __half2* hp = reinterpret_cast<const __half2*>(&hv);
        float2 f0 = __half22float2(hp[0]);
        float2 f1 = __half22float2(hp[1]);
        float4 s;
        s.x = f0.x; s.y = f0.y; s.z = f1.x; s.w = f1.y;
        out[(size_t)r * 32 + lane] = s;
    }
}

extern "C" void kernel_launch(void* const* d_in, const int* in_sizes, int n_in,
                              void* d_out, int out_size) {
    const float* level_tab    = (const float*)d_in[0];
    const float* type_tab     = (const float*)d_in[1];
    const float* feature_tab  = (const float*)d_in[2];
    const float* exchange_tab = (const float*)d_in[3];
    const float* pair_tab     = (const float*)d_in[4];
    const float* W            = (const float*)d_in[5];
    const float* b            = (const float*)d_in[6];
    const int* level_idx      = (const int*)d_in[7];
    const int* type_idx       = (const int*)d_in[8];
    const int* feature_idx    = (const int*)d_in[9];
    const int* exchange_idx   = (const int*)d_in[10];
    const int* pair_idx       = (const int*)d_in[11];

    int n = in_sizes[7];   // N rows

    int sm_count = 148;
    cudaDeviceGetAttribute(&sm_count, cudaDevAttrMultiProcessorCount, 0);

    // 160 blocks x 8 warps = exactly 1280 warp-tasks, one per warp.
    base_kernel<<<160, 256>>>(level_tab, type_tab, feature_tab,
                              exchange_tab, pair_tab, W, b);
    expand_kernel<<<4 * sm_count, 256>>>();

    // 6 blocks/SM x 256 threads = 48 warps/SM, no smem
    gather_kernel<<<6 * sm_count, 256>>>(level_idx, type_idx, feature_idx,
                                         exchange_idx, pair_idx,
                                         (float4*)d_out, n);
}

// round 14
// speedup vs baseline: 1.0010x; 1.0010x over previous
#include <cuda_runtime.h>
#include <cuda_fp16.h>

#define EMBED 128
#define ATTR 25
#define REM 28
#define PAIR_PAD 29                  // coprime with 32 -> conflict-free LDS
#define NLEVEL 50
#define NCOMB 240                    // 2*2*3*20
#define NFULL (NLEVEL * NCOMB)       // 12000 full-product rows

// Base projected tables (fp32, exact)
__device__ float g_Lrow[NLEVEL * EMBED];
__device__ float g_Crow[NCOMB * EMBED];
// Full product table, fp16: 3 MB (L2-resident)
__device__ __half g_Full[NFULL * EMBED];

// Grid-barrier state. g_count self-resets each barrier; g_sense flips per
// barrier (2 barriers/launch -> returns to 0: deterministic across replays).
__device__ unsigned g_count = 0;
__device__ volatile unsigned g_sense = 0;

// smem float offsets for staged raw tables (blocks 0..159 only)
#define S_LVL  0
#define S_TYP  (S_LVL + NLEVEL * ATTR)
#define S_FEA  (S_TYP + 2 * ATTR)
#define S_EXC  (S_FEA + 2 * ATTR)
#define S_PAI  (S_EXC + 3 * ATTR)
#define S_TOTAL (S_PAI + 20 * PAIR_PAD)        // 2005 floats ~ 8 KB

__device__ __forceinline__ void grid_barrier(unsigned nblocks, unsigned* sense_sm) {
    __syncthreads();
    if (threadIdx.x == 0) {
        unsigned want = (*sense_sm ^= 1u);
        __threadfence();                       // publish prior writes
        unsigned arrived = atomicAdd(&g_count, 1u);
        if (arrived == nblocks - 1u) {
            g_count = 0u;
            __threadfence();
            g_sense = want;                    // release
        } else {
            while (g_sense != want) __nanosleep(40);
        }
    }
    __syncthreads();
    __threadfence();                           // acquire
}

__global__ void __launch_bounds__(256, 6)
fused_all_kernel(const float* __restrict__ level_tab,
                 const float* __restrict__ type_tab,
                 const float* __restrict__ feature_tab,
                 const float* __restrict__ exchange_tab,
                 const float* __restrict__ pair_tab,
                 const float* __restrict__ W,
                 const float* __restrict__ b,
                 const int* __restrict__ level_idx,
                 const int* __restrict__ type_idx,
                 const int* __restrict__ feature_idx,
                 const int* __restrict__ exchange_idx,
                 const int* __restrict__ pair_idx,
                 float4* __restrict__ out, int n)
{
    __shared__ float sm[S_TOTAL];
    __shared__ unsigned sense_sm_arr[1];
    if (threadIdx.x == 0) sense_sm_arr[0] = 0u;

    const int tid  = threadIdx.x;
    const int lane = tid & 31;
    const unsigned nblocks = gridDim.x;

    // ================= Phase A: base rows (blocks 0..159 only) =================
    if (blockIdx.x < 160) {
        for (int i = tid; i < NLEVEL * ATTR; i += 256) sm[S_LVL + i] = level_tab[i];
        for (int i = tid; i < 2 * ATTR; i += 256)      sm[S_TYP + i] = type_tab[i];
        for (int i = tid; i < 2 * ATTR; i += 256)      sm[S_FEA + i] = feature_tab[i];
        for (int i = tid; i < 3 * ATTR; i += 256)      sm[S_EXC + i] = exchange_tab[i];
        for (int i = tid; i < 20 * REM; i += 256) {
            int p = i / REM, k = i - p * REM;
            sm[S_PAI + p * PAIR_PAD + k] = pair_tab[i];
        }
        __syncthreads();

        const int task = ((int)blockIdx.x << 3) + (tid >> 5);   // 0..1279
        if (task < 256) {
            int e = task >> 1;
            int r = ((task & 1) << 5) + lane;
            if (r < NLEVEL) {
                const float* wrow = W + e * EMBED;
                const float* lt = sm + S_LVL + r * ATTR;
                float s0 = 0.f, s1 = 0.f, s2 = 0.f, s3 = 0.f;
                #pragma unroll
                for (int k = 0; k < 24; k += 4) {
                    s0 += lt[k]     * wrow[k];
                    s1 += lt[k + 1] * wrow[k + 1];
                    s2 += lt[k + 2] * wrow[k + 2];
                    s3 += lt[k + 3] * wrow[k + 3];
                }
                s0 += lt[24] * wrow[24];
                g_Lrow[r * EMBED + e] = (s0 + s1) + (s2 + s3);
            }
        } else {
            int tt = task - 256;
            int e  = tt >> 3;
            int c  = ((tt & 7) << 5) + lane;
            if (c < NCOMB) {
                int p = c % 20, x = (c / 20) % 3, f = (c / 60) % 2, t = c / 120;
                const float* wrow = W + e * EMBED;
                const float* ta = sm + S_TYP + t * ATTR;
                const float* fa = sm + S_FEA + f * ATTR;
                const float* xa = sm + S_EXC + x * ATTR;
                const float* pa = sm + S_PAI + p * PAIR_PAD;
                float s0 = b[e], s1 = 0.f, s2 = 0.f, s3 = 0.f;
                #pragma unroll
                for (int k = 0; k < ATTR; k++) {
                    s0 += ta[k] * wrow[25 + k];
                    s1 += fa[k] * wrow[50 + k];
                    s2 += xa[k] * wrow[75 + k];
                }
                #pragma unroll
                for (int k = 0; k < REM; k++)
                    s3 += pa[k] * wrow[100 + k];
                g_Crow[c * EMBED + e] = (s0 + s1) + (s2 + s3);
            }
        }
    }

    grid_barrier(nblocks, sense_sm_arr);

    // ================= Phase B: expand to fp16 full table (all blocks) =========
    {
        const int total = NFULL * (EMBED / 2);      // 768000 half2 items
        __half2* full2 = reinterpret_cast<__half2*>(g_Full);
        for (int i = blockIdx.x * 256 + tid; i < total; i += nblocks * 256) {
            int row = i >> 6;
            int pos = (i & 63) << 1;
            int l = row / NCOMB;
            int c = row - l * NCOMB;
            float s0 = g_Lrow[l * EMBED + pos]     + g_Crow[c * EMBED + pos];
            float s1 = g_Lrow[l * EMBED + pos + 1] + g_Crow[c * EMBED + pos + 1];
            full2[i] = __floats2half2_rn(s0, s1);
        }
    }

    grid_barrier(nblocks, sense_sm_arr);

    // ================= Phase C: streaming gather (proven at DRAM floor) ========
    {
        const uint2* full2 = reinterpret_cast<const uint2*>(g_Full);
        const int warp   = (blockIdx.x * 256 + tid) >> 5;
        const int nwarps = (nblocks * 256) >> 5;

        int r = warp * 8;
        const int stride = nwarps * 8;

        for (; r + 7 < n; r += stride) {
            int4 L0 = *reinterpret_cast<const int4*>(level_idx + r);
            int4 L1 = *reinterpret_cast<const int4*>(level_idx + r + 4);
            int4 T0 = *reinterpret_cast<const int4*>(type_idx + r);
            int4 T1 = *reinterpret_cast<const int4*>(type_idx + r + 4);
            int4 F0 = *reinterpret_cast<const int4*>(feature_idx + r);
            int4 F1 = *reinterpret_cast<const int4*>(feature_idx + r + 4);
            int4 X0 = *reinterpret_cast<const int4*>(exchange_idx + r);
            int4 X1 = *reinterpret_cast<const int4*>(exchange_idx + r + 4);
            int4 P0 = *reinterpret_cast<const int4*>(pair_idx + r);
            int4 P1 = *reinterpret_cast<const int4*>(pair_idx + r + 4);

            int l[8] = {L0.x, L0.y, L0.z, L0.w, L1.x, L1.y, L1.z, L1.w};
            int t[8] = {T0.x, T0.y, T0.z, T0.w, T1.x, T1.y, T1.z, T1.w};
            int f[8] = {F0.x, F0.y, F0.z, F0.w, F1.x, F1.y, F1.z, F1.w};
            int x[8] = {X0.x, X0.y, X0.z, X0.w, X1.x, X1.y, X1.z, X1.w};
            int p[8] = {P0.x, P0.y, P0.z, P0.w, P1.x, P1.y, P1.z, P1.w};

            uint2 hv[8];
            #pragma unroll
            for (int k = 0; k < 8; k++) {
                int row = l[k] * NCOMB + ((t[k] * 2 + f[k]) * 3 + x[k]) * 20 + p[k];
                hv[k] = __ldg(&full2[row * 32 + lane]);
            }
            #pragma unroll
            for (int k = 0; k < 8; k++) {
                const __half2* hp = reinterpret_cast<const __half2*>(&hv[k]);
                float2 f0 = __half22float2(hp[0]);
                float2 f1 = __half22float2(hp[1]);
                float4 s;
                s.x = f0.x; s.y = f0.y; s.z = f1.x; s.w = f1.y;
                __stcs(out + (size_t)(r + k) * 32 + lane, s);
            }
        }
        for (; r < n; r++) {   // tail
            int row = level_idx[r] * NCOMB
                    + ((type_idx[r] * 2 + feature_idx[r]) * 3 + exchange_idx[r]) * 20
                    + pair_idx[r];
            uint2 hv = __ldg(&full2[row * 32 + lane]);
            const __half2* hp = reinterpret_cast<const __half2*>(&hv);
            float2 f0 = __half22float2(hp[0]);
            float2 f1 = __half22float2(hp[1]);
            float4 s;
            s.x = f0.x; s.y = f0.y; s.z = f1.x; s.w = f1.y;
            out[(size_t)r * 32 + lane] = s;
        }
    }
}

extern "C" void kernel_launch(void* const* d_in, const int* in_sizes, int n_in,
                              void* d_out, int out_size) {
    const float* level_tab    = (const float*)d_in[0];
    const float* type_tab     = (const float*)d_in[1];
    const float* feature_tab  = (const float*)d_in[2];
    const float* exchange_tab = (const float*)d_in[3];
    const float* pair_tab     = (const float*)d_in[4];
    const float* W            = (const float*)d_in[5];
    const float* b            = (const float*)d_in[6];
    const int* level_idx      = (const int*)d_in[7];
    const int* type_idx       = (const int*)d_in[8];
    const int* feature_idx    = (const int*)d_in[9];
    const int* exchange_idx   = (const int*)d_in[10];
    const int* pair_idx       = (const int*)d_in[11];

    int n = in_sizes[7];   // N rows

    int sm_count = 148;
    cudaDeviceGetAttribute(&sm_count, cudaDevAttrMultiProcessorCount, 0);

    // 6 blocks/SM x 256 threads: ALL blocks resident -> grid barrier is safe.
    fused_all_kernel<<<6 * sm_count, 256>>>(
        level_tab, type_tab, feature_tab, exchange_tab, pair_tab, W, b,
        level_idx, type_idx, feature_idx, exchange_idx, pair_idx,
        (float4*)d_out, n);
}

// round 15
// speedup vs baseline: 1.0833x; 1.0823x over previous
#include <cuda_runtime.h>
#include <cuda_fp16.h>

#define EMBED 128
#define ATTR 25
#define REM 28
#define PAIR_PAD 29                  // coprime with 32 -> conflict-free LDS
#define NLEVEL 50
#define NCOMB 240                    // 2*2*3*20

// fp16 projected tables (b folded into combined rows); 74.2 KB total -> L2/L1 hot
__device__ __half g_Lh[NLEVEL * EMBED];
__device__ __half g_Ch[NCOMB * EMBED];

// Grid-barrier state. Two barriers per launch (one functional, one trailing)
// -> g_sense returns to 0 every replay: deterministic under graph capture.
__device__ unsigned g_count = 0;
__device__ volatile unsigned g_sense = 0;

// smem float offsets for staged raw tables (blocks 0..159 only)
#define S_LVL  0
#define S_TYP  (S_LVL + NLEVEL * ATTR)
#define S_FEA  (S_TYP + 2 * ATTR)
#define S_EXC  (S_FEA + 2 * ATTR)
#define S_PAI  (S_EXC + 3 * ATTR)
#define S_TOTAL (S_PAI + 20 * PAIR_PAD)        // 2005 floats ~ 8 KB

__device__ __forceinline__ void grid_barrier(unsigned nblocks, unsigned* sense_sm) {
    __syncthreads();
    if (threadIdx.x == 0) {
        unsigned want = (*sense_sm ^= 1u);
        __threadfence();                       // publish prior writes
        unsigned arrived = atomicAdd(&g_count, 1u);
        if (arrived == nblocks - 1u) {
            g_count = 0u;
            __threadfence();
            g_sense = want;                    // release
        } else {
            while (g_sense != want) __nanosleep(40);
        }
    }
    __syncthreads();
    __threadfence();                           // acquire
}

__global__ void __launch_bounds__(256, 6)
fused_all_kernel(const float* __restrict__ level_tab,
                 const float* __restrict__ type_tab,
                 const float* __restrict__ feature_tab,
                 const float* __restrict__ exchange_tab,
                 const float* __restrict__ pair_tab,
                 const float* __restrict__ W,
                 const float* __restrict__ b,
                 const int* __restrict__ level_idx,
                 const int* __restrict__ type_idx,
                 const int* __restrict__ feature_idx,
                 const int* __restrict__ exchange_idx,
                 const int* __restrict__ pair_idx,
                 float4* __restrict__ out, int n)
{
    __shared__ float sm[S_TOTAL];
    __shared__ unsigned sense_sm_arr[1];
    if (threadIdx.x == 0) sense_sm_arr[0] = 0u;

    const int tid  = threadIdx.x;
    const int lane = tid & 31;
    const unsigned nblocks = gridDim.x;

    // ====== Phase A: project base tables to fp16 (blocks 0..159; 1280 warp-tasks) ======
    if (blockIdx.x < 160) {
        for (int i = tid; i < NLEVEL * ATTR; i += 256) sm[S_LVL + i] = level_tab[i];
        for (int i = tid; i < 2 * ATTR; i += 256)      sm[S_TYP + i] = type_tab[i];
        for (int i = tid; i < 2 * ATTR; i += 256)      sm[S_FEA + i] = feature_tab[i];
        for (int i = tid; i < 3 * ATTR; i += 256)      sm[S_EXC + i] = exchange_tab[i];
        for (int i = tid; i < 20 * REM; i += 256) {
            int p = i / REM, k = i - p * REM;
            sm[S_PAI + p * PAIR_PAD + k] = pair_tab[i];
        }
        __syncthreads();

        const int task = ((int)blockIdx.x << 3) + (tid >> 5);   // 0..1279
        if (task < 256) {
            // level rows: task = e*2 + rb; lanes span r
            int e = task >> 1;
            int r = ((task & 1) << 5) + lane;
            if (r < NLEVEL) {
                const float* wrow = W + e * EMBED;       // broadcast
                const float* lt = sm + S_LVL + r * ATTR; // stride-25 LDS, conflict-free
                float s0 = 0.f, s1 = 0.f, s2 = 0.f, s3 = 0.f;
                #pragma unroll
                for (int k = 0; k < 24; k += 4) {
                    s0 += lt[k]     * wrow[k];
                    s1 += lt[k + 1] * wrow[k + 1];
                    s2 += lt[k + 2] * wrow[k + 2];
                    s3 += lt[k + 3] * wrow[k + 3];
                }
                s0 += lt[24] * wrow[24];
                g_Lh[r * EMBED + e] = __float2half_rn((s0 + s1) + (s2 + s3));
            }
        } else {
            // combined rows: task-256 = e*8 + cb; lanes span c; b folded in
            int tt = task - 256;
            int e  = tt >> 3;
            int c  = ((tt & 7) << 5) + lane;
            if (c < NCOMB) {
                int p = c % 20, x = (c / 20) % 3, f = (c / 60) % 2, t = c / 120;
                const float* wrow = W + e * EMBED;
                const float* ta = sm + S_TYP + t * ATTR;
                const float* fa = sm + S_FEA + f * ATTR;
                const float* xa = sm + S_EXC + x * ATTR;
                const float* pa = sm + S_PAI + p * PAIR_PAD;
                float s0 = b[e], s1 = 0.f, s2 = 0.f, s3 = 0.f;
                #pragma unroll
                for (int k = 0; k < ATTR; k++) {
                    s0 += ta[k] * wrow[25 + k];
                    s1 += fa[k] * wrow[50 + k];
                    s2 += xa[k] * wrow[75 + k];
                }
                #pragma unroll
                for (int k = 0; k < REM; k++)
                    s3 += pa[k] * wrow[100 + k];
                g_Ch[c * EMBED + e] = __float2half_rn((s0 + s1) + (s2 + s3));
            }
        }
    }

    grid_barrier(nblocks, sense_sm_arr);    // sense -> 1

    // ====== Phase C: streaming gather, 2 fp16 row-loads per output row ======
    {
        const uint2* L2h = reinterpret_cast<const uint2*>(g_Lh);   // 32 uint2 per row
        const uint2* C2h = reinterpret_cast<const uint2*>(g_Ch);
        const int warp   = (blockIdx.x * 256 + tid) >> 5;
        const int nwarps = (nblocks * 256) >> 5;

        int r = warp * 4;
        const int stride = nwarps * 4;

        for (; r + 3 < n; r += stride) {
            int4 L = *reinterpret_cast<const int4*>(level_idx + r);
            int4 T = *reinterpret_cast<const int4*>(type_idx + r);
            int4 F = *reinterpret_cast<const int4*>(feature_idx + r);
            int4 X = *reinterpret_cast<const int4*>(exchange_idx + r);
            int4 P = *reinterpret_cast<const int4*>(pair_idx + r);

            int l[4] = {L.x, L.y, L.z, L.w};
            int t[4] = {T.x, T.y, T.z, T.w};
            int f[4] = {F.x, F.y, F.z, F.w};
            int x[4] = {X.x, X.y, X.z, X.w};
            int p[4] = {P.x, P.y, P.z, P.w};

            uint2 hvA[4], hvQ[4];
            #pragma unroll
            for (int k = 0; k < 4; k++) {
                int c = ((t[k] * 2 + f[k]) * 3 + x[k]) * 20 + p[k];
                hvA[k] = __ldg(&L2h[l[k] * 32 + lane]);
                hvQ[k] = __ldg(&C2h[c * 32 + lane]);
            }
            #pragma unroll
            for (int k = 0; k < 4; k++) {
                const __half2* ah = reinterpret_cast<const __half2*>(&hvA[k]);
                const __half2* qh = reinterpret_cast<const __half2*>(&hvQ[k]);
                float2 a0 = __half22float2(ah[0]);
                float2 a1 = __half22float2(ah[1]);
                float2 q0 = __half22float2(qh[0]);
                float2 q1 = __half22float2(qh[1]);
                float4 s;
                s.x = a0.x + q0.x;
                s.y = a0.y + q0.y;
                s.z = a1.x + q1.x;
                s.w = a1.y + q1.y;
                __stcs(out + (size_t)(r + k) * 32 + lane, s);
            }
        }
        for (; r < n; r++) {   // tail
            int c = ((type_idx[r] * 2 + feature_idx[r]) * 3 + exchange_idx[r]) * 20
                  + pair_idx[r];
            uint2 A = __ldg(&L2h[level_idx[r] * 32 + lane]);
            uint2 Q = __ldg(&C2h[c * 32 + lane]);
            const __half2* ah = reinterpret_cast<const __half2*>(&A);
            const __half2* qh = reinterpret_cast<const __half2*>(&Q);
            float2 a0 = __half22float2(ah[0]);
            float2 a1 = __half22float2(ah[1]);
            float2 q0 = __half22float2(qh[0]);
            float2 q1 = __half22float2(qh[1]);
            float4 s;
            s.x = a0.x + q0.x;
            s.y = a0.y + q0.y;
            s.z = a1.x + q1.x;
            s.w = a1.y + q1.y;
            out[(size_t)r * 32 + lane] = s;
        }
    }

    // Trailing barrier: restores g_sense to 0 for the next graph replay.
    // Costs nothing — kernel already ends with the slowest block.
    grid_barrier(nblocks, sense_sm_arr);    // sense -> 0
}

extern "C" void kernel_launch(void* const* d_in, const int* in_sizes, int n_in,
                              void* d_out, int out_size) {
    const float* level_tab    = (const float*)d_in[0];
    const float* type_tab     = (const float*)d_in[1];
    const float* feature_tab  = (const float*)d_in[2];
    const float* exchange_tab = (const float*)d_in[3];
    const float* pair_tab     = (const float*)d_in[4];
    const float* W            = (const float*)d_in[5];
    const float* b            = (const float*)d_in[6];
    const int* level_idx      = (const int*)d_in[7];
    const int* type_idx       = (const int*)d_in[8];
    const int* feature_idx    = (const int*)d_in[9];
    const int* exchange_idx   = (const int*)d_in[10];
    const int* pair_idx       = (const int*)d_in[11];

    int n = in_sizes[7];   // N rows

    int sm_count = 148;
    cudaDeviceGetAttribute(&sm_count, cudaDevAttrMultiProcessorCount, 0);

    // 6 blocks/SM x 256 threads: ALL blocks resident -> grid barrier is safe.
    fused_all_kernel<<<6 * sm_count, 256>>>(
        level_tab, type_tab, feature_tab, exchange_tab, pair_tab, W, b,
        level_idx, type_idx, feature_idx, exchange_idx, pair_idx,
        (float4*)d_out, n);
}